// round 7
// baseline (speedup 1.0000x reference)
#include <cuda_runtime.h>

// NbitTreeDecoder: one thread per level-9 node (262144 threads, 55 warps/SM for
// latency hiding) with the lean arithmetic path:
//   - smem LUT: packed set-bit positions (low16) + their 3-bit reversals (high16)
//   - X = (p27<<3)|j9; Xr = brev32(X)>>2 = (brev32(p27)>>5) | (rev3(j9)<<27)
//     -> x,y fields shared by the node's 4 leaves; only z varies per leaf
//   - float(field) = __uint_as_float(0x4B000000|field) - 2^23  (exact)

#define MAGIC  0x4B000000u
#define MAGICF 8388608.0f

struct Lut { unsigned v[256]; };
__host__ __device__ constexpr Lut make_lut() {
    Lut l{};
    for (int f = 0; f < 256; f++) {
        unsigned jp = 0u, rp = 0u; int cnt = 0;
        for (int b = 0; b < 8 && cnt < 4; b++) {
            if (f & (1 << b)) {
                unsigned r3 = (unsigned)(((b & 1) << 2) | (b & 2) | ((b >> 2) & 1));
                jp |= (unsigned)b << (4 * cnt);
                rp |= r3 << (4 * cnt);
                cnt++;
            }
        }
        l.v[f] = jp | (rp << 16);
    }
    return l;
}
__device__ constexpr Lut g_lut = make_lut();

__global__ void __launch_bounds__(256)
decode_kernel(const int* __restrict__ flags,
              const float* __restrict__ offset,
              const float* __restrict__ scale,
              float* __restrict__ out)
{
    __shared__ unsigned slut[256];
    const unsigned tid = threadIdx.x;
    slut[tid] = g_lut.v[tid];

    const unsigned n9 = blockIdx.x * 256u + tid;   // [0, 4^9)
    const unsigned n8 = n9 >> 2;

    // ---- all global loads up front (addresses depend only on thread id) ----
    const unsigned OFF[8] = {0u, 1u, 5u, 21u, 85u, 341u, 1365u, 5461u};
    unsigned fl[8];
#pragma unroll
    for (int t = 0; t < 8; t++)
        fl[t] = (unsigned)__ldg(flags + OFF[t] + (n8 >> (16 - 2 * t)));
    const unsigned f8 = (unsigned)__ldg(flags + 21845u + n8);
    const unsigned f9 = (unsigned)__ldg(flags + 87381u + n9);

    const float2 s01 = __ldg(reinterpret_cast<const float2*>(scale));
    const float  s2  = __ldg(scale + 2);
    const float2 o01 = __ldg(reinterpret_cast<const float2*>(offset));
    const float  o2  = __ldg(offset + 2);

    __syncthreads();

    // ---- levels 0..7 prefix via LUT bit-rank (independent lookups) ----
    unsigned prefix = 0u;
#pragma unroll
    for (int t = 0; t < 8; t++) {
        const unsigned d = (n8 >> (14 - 2 * t)) & 3u;
        prefix = (prefix << 3) | ((slut[fl[t]] >> (4u * d)) & 7u);
    }

    // ---- level 8 digit for this node ----
    const unsigned d8 = n9 & 3u;
    const unsigned p  = (prefix << 3) | ((slut[f8] >> (4u * d8)) & 7u);  // 27-bit

    // ---- shared x, y; per-leaf z ----
    const unsigned B = __brev(p) >> 5;
    const float x = fmaf(__uint_as_float(MAGIC | (B & 1023u)) - MAGICF, s01.x, o01.x);
    const float y = fmaf(__uint_as_float(MAGIC | ((B >> 10) & 1023u)) - MAGICF, s01.y, o01.y);

    const unsigned M2 = MAGIC | (B >> 20);
    const unsigned rp = slut[f9] >> 16;            // packed rev3 of the 4 set bits

    float z[4];
#pragma unroll
    for (int d = 0; d < 4; d++)
        z[d] = fmaf(__uint_as_float(M2 | (((rp >> (4 * d)) & 7u) << 7)) - MAGICF, s2, o2);

    // ---- 4 leaves * 12B = 48B contiguous, 16B-aligned -> 3x STG.128 ----
    float4* outv = reinterpret_cast<float4*>(out + (size_t)n9 * 12u);
    outv[0] = make_float4(x,    y,    z[0], x);
    outv[1] = make_float4(y,    z[1], x,    y);
    outv[2] = make_float4(z[2], x,    y,    z[3]);
}

extern "C" void kernel_launch(void* const* d_in, const int* in_sizes, int n_in,
                              void* d_out, int out_size) {
    const int*   flags  = (const int*)d_in[0];
    const float* offset = (const float*)d_in[1];
    const float* scale  = (const float*)d_in[2];
    float*       out    = (float*)d_out;

    decode_kernel<<<1024, 256>>>(flags, offset, scale, out);
}

// round 8
// speedup vs baseline: 1.0145x; 1.0145x over previous
#include <cuda_runtime.h>

// NbitTreeDecoder R8: pair-of-level-9-nodes per thread (131072 threads,
// 1024 x 128), 96B contiguous output per thread via 3x st.global.v8.f32.
// No shared memory, no syncs: all bit-rank selection on the ALU pipe
// (predicated clear-lowest-set chains + __ffs), 3-bit reversal in registers.
//
// Identities (validated rounds 1-7, rel_err 2.9e-8):
//   X = (p27<<3)|j9 ; brev32(X)>>2 = (brev32(p27)>>5) | (rev3(j9)<<27)
//   -> x,y fields shared per level-9 node; z = (B>>20) | (rev3(j9)<<7)
//   float(field) = __uint_as_float(0x4B000000|field) - 2^23   (exact)

#define MAGIC  0x4B000000u
#define MAGICF 8388608.0f

static __device__ __forceinline__ unsigned nth_set_bit(unsigned f, unsigned d) {
    unsigned g = f;
    g = (d > 0u) ? (g & (g - 1u)) : g;
    g = (d > 1u) ? (g & (g - 1u)) : g;
    g = (d > 2u) ? (g & (g - 1u)) : g;
    return (unsigned)__ffs(g) - 1u;
}

static __device__ __forceinline__ unsigned rev3(unsigned j) {
    return ((j & 1u) << 2) | (j & 2u) | ((j >> 2) & 1u);
}

#define STG256(ptr, a0,a1,a2,a3,a4,a5,a6,a7)                                  \
    asm volatile("st.global.v8.f32 [%0], {%1,%2,%3,%4,%5,%6,%7,%8};"          \
                 :: "l"(ptr), "f"(a0), "f"(a1), "f"(a2), "f"(a3),             \
                    "f"(a4), "f"(a5), "f"(a6), "f"(a7) : "memory")

__global__ void __launch_bounds__(128)
decode_kernel(const int* __restrict__ flags,
              const float* __restrict__ offset,
              const float* __restrict__ scale,
              float* __restrict__ out)
{
    const unsigned i  = blockIdx.x * 128u + threadIdx.x;  // level-9 node pair id
    const unsigned n8 = i >> 1;                           // shared level-8 parent

    // ---- all global loads up front (addresses depend only on thread id) ----
    const unsigned OFF[8] = {0u, 1u, 5u, 21u, 85u, 341u, 1365u, 5461u};
    unsigned fl[8];
#pragma unroll
    for (int t = 0; t < 8; t++)
        fl[t] = (unsigned)__ldg(flags + OFF[t] + (n8 >> (16 - 2 * t)));
    const unsigned f8  = (unsigned)__ldg(flags + 21845u + n8);
    const unsigned f9a = (unsigned)__ldg(flags + 87381u + 2u * i);
    const unsigned f9b = (unsigned)__ldg(flags + 87381u + 2u * i + 1u);

    const float2 s01 = __ldg(reinterpret_cast<const float2*>(scale));
    const float  s2  = __ldg(scale + 2);
    const float2 o01 = __ldg(reinterpret_cast<const float2*>(offset));
    const float  o2  = __ldg(offset + 2);

    // ---- levels 0..7: 24-bit prefix (ALU bit-rank) ----
    unsigned prefix = 0u;
#pragma unroll
    for (int t = 0; t < 8; t++) {
        const unsigned d = (n8 >> (14 - 2 * t)) & 3u;
        prefix = (prefix << 3) | nth_set_bit(fl[t], d);
    }

    // ---- level 8: this thread's two children carry digits 2i&3, (2i+1)&3 ----
    const unsigned da = (2u * i) & 3u;
    const unsigned pa = (prefix << 3) | nth_set_bit(f8, da);
    const unsigned pb = (prefix << 3) | nth_set_bit(f8, da + 1u);

    // ---- shared x,y per node; per-leaf z ----
    const unsigned Ba = __brev(pa) >> 5;
    const unsigned Bb = __brev(pb) >> 5;

    const float xa = fmaf(__uint_as_float(MAGIC | (Ba & 1023u)) - MAGICF, s01.x, o01.x);
    const float ya = fmaf(__uint_as_float(MAGIC | ((Ba >> 10) & 1023u)) - MAGICF, s01.y, o01.y);
    const float xb = fmaf(__uint_as_float(MAGIC | (Bb & 1023u)) - MAGICF, s01.x, o01.x);
    const float yb = fmaf(__uint_as_float(MAGIC | ((Bb >> 10) & 1023u)) - MAGICF, s01.y, o01.y);

    const unsigned Ma = MAGIC | (Ba >> 20);
    const unsigned Mb = MAGIC | (Bb >> 20);

    float za[4], zb[4];
    unsigned ga = f9a, gb = f9b;
#pragma unroll
    for (int d = 0; d < 4; d++) {
        const unsigned jla = (unsigned)__ffs(ga) - 1u;  ga &= ga - 1u;
        const unsigned jlb = (unsigned)__ffs(gb) - 1u;  gb &= gb - 1u;
        za[d] = fmaf(__uint_as_float(Ma | (rev3(jla) << 7)) - MAGICF, s2, o2);
        zb[d] = fmaf(__uint_as_float(Mb | (rev3(jlb) << 7)) - MAGICF, s2, o2);
    }

    // ---- 8 leaves * 12B = 96B contiguous, 32B-aligned -> 3x STG.256 ----
    float* o = out + (size_t)i * 24u;
    STG256(o,      xa,    ya,    za[0], xa,    ya,    za[1], xa,    ya   );
    STG256(o + 8,  za[2], xa,    ya,    za[3], xb,    yb,    zb[0], xb   );
    STG256(o + 16, yb,    zb[1], xb,    yb,    zb[2], xb,    yb,    zb[3]);
}

extern "C" void kernel_launch(void* const* d_in, const int* in_sizes, int n_in,
                              void* d_out, int out_size) {
    const int*   flags  = (const int*)d_in[0];
    const float* offset = (const float*)d_in[1];
    const float* scale  = (const float*)d_in[2];
    float*       out    = (float*)d_out;

    decode_kernel<<<1024, 128>>>(flags, offset, scale, out);
}